// round 7
// baseline (speedup 1.0000x reference)
#include <cuda_runtime.h>

#define NW    162
#define CCH   128          // channels
#define CV4   (CCH / 4)    // float4 per row
#define MAXN  65536
#define TILE  256
#define MAXT  (MAXN / TILE)

// Scratch (allocation-free rule: __device__ globals)
__device__ int g_counts[NW];
__device__ int g_offsets[NW];
__device__ int g_order[MAXN];
// COLUMN-MAJOR: g_tileHist[w * T + t]  (~104 KB for T=161 -> L2-resident)
__device__ int g_tileHist[NW * MAXT];

// ---------------- pass A: per-tile (256-elem) histogram, one block per tile
__global__ void k_hist(const int* __restrict__ wid, int N, int T) {
    __shared__ int sh[NW];
    const int tile = blockIdx.x;
    for (int i = threadIdx.x; i < NW; i += TILE) sh[i] = 0;
    __syncthreads();
    int i = tile * TILE + threadIdx.x;
    if (i < N) atomicAdd(&sh[wid[i]], 1);
    __syncthreads();
    for (int w = threadIdx.x; w < NW; w += TILE)
        g_tileHist[w * T + tile] = sh[w];
}

// ---------------- pass B (fused): per-window column scans + cross-window
// offsets + counts tail. ONE block, 1024 threads = 32 warps.
__global__ void k_scanfuse(int T, float* __restrict__ counts_f, int write_tail) {
    const int warp = threadIdx.x >> 5;
    const int lane = threadIdx.x & 31;

    // each warp scans columns w = warp, warp+32, ...
    for (int w = warp; w < NW; w += 32) {
        int* __restrict__ col = &g_tileHist[w * T];
        int carry = 0;
        for (int t0 = 0; t0 < T; t0 += 32) {
            int t = t0 + lane;
            int v = (t < T) ? col[t] : 0;
            int s = v;
#pragma unroll
            for (int d = 1; d < 32; d <<= 1) {
                int u = __shfl_up_sync(0xffffffffu, s, d);
                if (lane >= d) s += u;
            }
            if (t < T) col[t] = carry + s - v;   // exclusive
            carry += __shfl_sync(0xffffffffu, s, 31);
        }
        if (lane == 0) g_counts[w] = carry;
    }
    __syncthreads();

    // warp 0: exclusive scan of the 162 counts -> offsets
    if (warp == 0) {
        int carry = 0;
#pragma unroll
        for (int c0 = 0; c0 < NW; c0 += 32) {
            int w = c0 + lane;
            int v = (w < NW) ? g_counts[w] : 0;
            int s = v;
#pragma unroll
            for (int d = 1; d < 32; d <<= 1) {
                int u = __shfl_up_sync(0xffffffffu, s, d);
                if (lane >= d) s += u;
            }
            if (w < NW) g_offsets[w] = carry + s - v;
            carry += __shfl_sync(0xffffffffu, s, 31);
        }
    }
    if (write_tail) {
        for (int w = threadIdx.x; w < NW; w += 1024)
            counts_f[w] = (float)g_counts[w];
    }
}

// ---------------- pass C: stable rank + scatter of order (one block/tile)
__global__ void k_rank(const int* __restrict__ wid, int N, int T,
                       float* __restrict__ order_f, int write_tail) {
    __shared__ int wcnt[8 * NW];   // [warp][window] counts within this tile
    const int tile = blockIdx.x;
    const int i    = tile * TILE + threadIdx.x;
    const int lane = threadIdx.x & 31;
    const int wu   = threadIdx.x >> 5;

    for (int j = threadIdx.x; j < 8 * NW; j += TILE) wcnt[j] = 0;
    __syncthreads();

    unsigned active = __ballot_sync(0xffffffffu, i < N);
    int w = 0, rank = 0;
    bool ok = (i < N);
    if (ok) {
        w = wid[i];
        unsigned m = __match_any_sync(active, w);
        rank = __popc(m & ((1u << lane) - 1u));
        if (lane == (__ffs(m) - 1)) wcnt[wu * NW + w] = __popc(m);
    }
    __syncthreads();

    if (ok) {
        int pre = 0;
        for (int j = 0; j < wu; ++j) pre += wcnt[j * NW + w];
        int pos = g_offsets[w] + g_tileHist[w * T + tile] + pre + rank;
        g_order[pos] = i;
        if (write_tail) order_f[pos] = (float)i;
    }
}

// ---------------- gather: 8 rows per warp (MLP=8), streaming ld/st
__global__ void k_gather(const float4* __restrict__ x,
                         float4* __restrict__ out,
                         int N, int maxw, int rows) {
    int warp = (int)(((long long)blockIdx.x * blockDim.x + threadIdx.x) >> 5);
    int lane = threadIdx.x & 31;
    int r0 = warp * 8;
    if (r0 >= rows) return;

    const int nwmax = NW * maxw;
    int src[8];
    bool valid[8];

#pragma unroll
    for (int j = 0; j < 8; ++j) {
        int r = r0 + j;
        valid[j] = false;
        src[j] = 0;
        if (r < rows) {
            int b   = r / nwmax;
            int rem = r - b * nwmax;
            int w   = rem / maxw;
            int p   = rem - w * maxw;
            if (p < g_counts[w]) {
                int idx  = g_order[g_offsets[w] + p];
                src[j]   = (b * N + idx) * CV4 + lane;   // < 2^31
                valid[j] = true;
            }
        }
    }

    float4 v[8];
#pragma unroll
    for (int j = 0; j < 8; ++j)
        v[j] = valid[j] ? __ldcs(&x[src[j]]) : make_float4(0.f, 0.f, 0.f, 0.f);

#pragma unroll
    for (int j = 0; j < 8; ++j)
        if (r0 + j < rows)
            __stcs(&out[(long long)(r0 + j) * CV4 + lane], v[j]);
}

extern "C" void kernel_launch(void* const* d_in, const int* in_sizes, int n_in,
                              void* d_out, int out_size) {
    const float* x   = (const float*)d_in[0];
    const int*   wid = (const int*)d_in[1];

    const int N = in_sizes[1];
    const int B = (int)(((long long)in_sizes[0]) / ((long long)N * CCH));
    const int T = (N + TILE - 1) / TILE;

    // Recover max_win_size (and output layout) from out_size.
    const long long denom = (long long)B * NW * CCH;   // elems per p-slot
    const long long tail  = (long long)N + NW;         // order + counts
    const long long osz   = (long long)out_size;

    int maxw, concat;
    if (osz >= tail && ((osz - tail) % denom) == 0) {
        concat = 1;
        maxw   = (int)((osz - tail) / denom);
    } else {
        concat = 0;
        maxw   = (int)(osz / denom);
    }

    float* out      = (float*)d_out;
    long long winEl = denom * (long long)maxw;
    float* order_f  = out + winEl;
    float* counts_f = order_f + N;

    k_hist<<<T, TILE>>>(wid, N, T);
    k_scanfuse<<<1, 1024>>>(T, counts_f, concat);
    k_rank<<<T, TILE>>>(wid, N, T, order_f, concat);

    int rows  = B * NW * maxw;
    int warps = (rows + 7) / 8;
    long long totThreads = (long long)warps * 32;
    int tgrid = (int)((totThreads + 255) / 256);
    k_gather<<<tgrid, 256>>>((const float4*)x, (float4*)out, N, maxw, rows);
}